// round 1
// baseline (speedup 1.0000x reference)
#include <cuda_runtime.h>
#include <cuda_bf16.h>

// Shapes (fixed by the problem)
#define Bb 4
#define Ll 2048
#define DM 1024
#define DI 2048
#define DS 64
#define DTR 64
#define XPJ 192           // DTR + 2*DS
#define BL  (Bb*Ll)       // 8192

// ---------------- scratch (device globals; no allocation APIs) --------------
__device__ float g_xn[BL * DM];        // 32 MB  layernorm output
__device__ float g_xz[BL * 2 * DI];    // 128 MB xz = xn @ W_in   (cols 0..2047 = xi, 2048..4095 = silu(z))
__device__ float g_u [BL * DI];        // 64 MB  conv+silu output
__device__ float g_xd[BL * XPJ];       // 6 MB   x_dbl
__device__ float g_dl[BL * DI];        // 64 MB  delta (post softplus)
__device__ float g_y [BL * DI];        // 64 MB  scan output * silu(z)

// ---------------- LayerNorm -------------------------------------------------
__global__ void ln_kernel(const float* __restrict__ x,
                          const float* __restrict__ w,
                          const float* __restrict__ b,
                          float* __restrict__ out) {
    int row = blockIdx.x;             // 0..BL-1
    int tid = threadIdx.x;            // 0..255, 4 floats each
    const float4* xr = (const float4*)(x + (size_t)row * DM);
    float4 v = xr[tid];

    __shared__ float s1[8], s2[8];
    float sum  = v.x + v.y + v.z + v.w;
    float sumq = v.x*v.x + v.y*v.y + v.z*v.z + v.w*v.w;
    for (int o = 16; o > 0; o >>= 1) {
        sum  += __shfl_xor_sync(0xffffffff, sum,  o);
        sumq += __shfl_xor_sync(0xffffffff, sumq, o);
    }
    if ((tid & 31) == 0) { s1[tid >> 5] = sum; s2[tid >> 5] = sumq; }
    __syncthreads();
    float ts = 0.f, tq = 0.f;
#pragma unroll
    for (int i = 0; i < 8; i++) { ts += s1[i]; tq += s2[i]; }
    float mu  = ts * (1.0f / DM);
    float var = tq * (1.0f / DM) - mu * mu;
    float inv = rsqrtf(var + 1e-5f);

    const float4 wv = ((const float4*)w)[tid];
    const float4 bv = ((const float4*)b)[tid];
    float4 o;
    o.x = (v.x - mu) * inv * wv.x + bv.x;
    o.y = (v.y - mu) * inv * wv.y + bv.y;
    o.z = (v.z - mu) * inv * wv.z + bv.z;
    o.w = (v.w - mu) * inv * wv.w + bv.w;
    ((float4*)(out + (size_t)row * DM))[tid] = o;
}

// ---------------- SGEMM (fp32, 128xBNx16 tiles, TMxTN micro-tile) -----------
// MODE 0: C = A*B
// MODE 1: C = A*B, with silu applied to columns >= halfN   (GEMM1: z half)
// MODE 2: C = softplus(A*B + bias[col])                    (GEMM3: delta)
// MODE 3: C = A*B + res[row*ldc+col]                       (GEMM4: +residual)
__device__ __forceinline__ float siluf(float v) { return v / (1.0f + __expf(-v)); }

template<int BM, int BN, int BK, int TM, int TN, int MODE>
__global__ __launch_bounds__(256) void sgemm_kernel(
    int M, int N, int K,
    const float* __restrict__ A, int lda,
    const float* __restrict__ B, int ldb,
    float* __restrict__ C, int ldc,
    const float* __restrict__ bias,
    const float* __restrict__ res,
    int halfN)
{
    constexpr int THREADS = (BM / TM) * (BN / TN);
    static_assert(THREADS == 256, "256 threads");
    __shared__ float As[BK][BM];
    __shared__ float Bs[BK][BN];

    const int tid = threadIdx.x;
    const int threadCol = tid % (BN / TN);
    const int threadRow = tid / (BN / TN);

    const int rowBase = blockIdx.y * BM;
    const int colBase = blockIdx.x * BN;

    // A-tile load mapping (float4)
    const int rowA  = tid / (BK / 4);
    const int colA4 = (tid % (BK / 4)) * 4;
    constexpr int A_ROW_STRIDE = THREADS / (BK / 4);
    constexpr int A_ITERS = BM / A_ROW_STRIDE;
    // B-tile load mapping (float4)
    const int rowB  = tid / (BN / 4);
    const int colB4 = (tid % (BN / 4)) * 4;
    constexpr int B_ROW_STRIDE = THREADS / (BN / 4);
    constexpr int B_ITERS = BK / B_ROW_STRIDE;

    float acc[TM][TN];
#pragma unroll
    for (int i = 0; i < TM; i++)
#pragma unroll
        for (int j = 0; j < TN; j++) acc[i][j] = 0.f;

    float regM[TM], regN[TN];

    for (int k0 = 0; k0 < K; k0 += BK) {
        // load A tile (transposed into smem)
#pragma unroll
        for (int it = 0; it < A_ITERS; it++) {
            int r = rowA + it * A_ROW_STRIDE;
            float4 v = *(const float4*)(A + (size_t)(rowBase + r) * lda + k0 + colA4);
            As[colA4 + 0][r] = v.x;
            As[colA4 + 1][r] = v.y;
            As[colA4 + 2][r] = v.z;
            As[colA4 + 3][r] = v.w;
        }
        // load B tile
#pragma unroll
        for (int it = 0; it < B_ITERS; it++) {
            int r = rowB + it * B_ROW_STRIDE;
            float4 v = *(const float4*)(B + (size_t)(k0 + r) * ldb + colBase + colB4);
            *(float4*)&Bs[r][colB4] = v;
        }
        __syncthreads();

#pragma unroll
        for (int k = 0; k < BK; k++) {
#pragma unroll
            for (int i = 0; i < TM; i += 4)
                *(float4*)&regM[i] = *(const float4*)&As[k][threadRow * TM + i];
#pragma unroll
            for (int j = 0; j < TN; j += 4)
                *(float4*)&regN[j] = *(const float4*)&Bs[k][threadCol * TN + j];
#pragma unroll
            for (int i = 0; i < TM; i++)
#pragma unroll
                for (int j = 0; j < TN; j++)
                    acc[i][j] = fmaf(regM[i], regN[j], acc[i][j]);
        }
        __syncthreads();
    }

    // epilogue
#pragma unroll
    for (int i = 0; i < TM; i++) {
        int row = rowBase + threadRow * TM + i;
#pragma unroll
        for (int j = 0; j < TN; j++) {
            int col = colBase + threadCol * TN + j;
            float v = acc[i][j];
            if (MODE == 1) {
                if (col >= halfN) v = siluf(v);
            } else if (MODE == 2) {
                v += bias[col];
                v = (v > 20.0f) ? v : log1pf(expf(v));
            } else if (MODE == 3) {
                v += res[(size_t)row * ldc + col];
            }
            C[(size_t)row * ldc + col] = v;
        }
    }
}

// ---------------- depthwise causal conv (k=4) + bias + silu -----------------
__global__ void conv_kernel(const float* __restrict__ cw,
                            const float* __restrict__ cb) {
    int idx = blockIdx.x * blockDim.x + threadIdx.x;  // over BL*DI
    if (idx >= BL * DI) return;
    int d = idx & (DI - 1);
    int r = idx >> 11;          // row in BL (DI = 2048 = 2^11)
    int l = r & (Ll - 1);

    float s = cb[d];
    const float* w = cw + d * 4;
#pragma unroll
    for (int k = 0; k < 4; k++) {
        int lt = l - 3 + k;
        if (lt >= 0) s += w[k] * g_xz[(size_t)(r - 3 + k) * (2 * DI) + d];
    }
    g_u[(size_t)r * DI + d] = s / (1.0f + __expf(-s));   // silu
}

// ---------------- selective scan: one warp per (b, d) channel ---------------
__global__ __launch_bounds__(256) void scan_kernel(const float* __restrict__ A_log,
                                                   const float* __restrict__ Dw) {
    const int warp = (blockIdx.x * blockDim.x + threadIdx.x) >> 5;  // 0..8191
    const int lane = threadIdx.x & 31;
    const int b = warp >> 11;       // / DI
    const int d = warp & (DI - 1);

    // lane owns states n0 = 2*lane, n1 = 2*lane+1
    const int n0 = 2 * lane;
    // a' = A * log2(e)  where A = -exp(A_log)
    float aa0 = -__expf(A_log[(size_t)d * DS + n0])     * 1.44269504088896f;
    float aa1 = -__expf(A_log[(size_t)d * DS + n0 + 1]) * 1.44269504088896f;
    const float Dd = Dw[d];

    const size_t rowBase = (size_t)b * Ll;
    float h0 = 0.f, h1 = 0.f;

    for (int t = 0; t < Ll; t++) {
        const size_t r = rowBase + t;
        float dt  = g_dl[r * DI + d];                 // broadcast load
        float ut  = g_u [r * DI + d];
        float zs  = g_xz[r * (2 * DI) + DI + d];      // silu(z), fused in GEMM1
        float2 Bv = *(const float2*)&g_xd[r * XPJ + DTR + n0];
        float2 Cv = *(const float2*)&g_xd[r * XPJ + DTR + DS + n0];

        float e0 = exp2f(dt * aa0);
        float e1 = exp2f(dt * aa1);
        float du = dt * ut;
        h0 = fmaf(h0, e0, du * Bv.x);
        h1 = fmaf(h1, e1, du * Bv.y);
        float p = fmaf(h0, Cv.x, h1 * Cv.y);
#pragma unroll
        for (int o = 16; o > 0; o >>= 1)
            p += __shfl_xor_sync(0xffffffff, p, o);
        if (lane == 0)
            g_y[r * DI + d] = (p + ut * Dd) * zs;
    }
}

// ---------------- launch ----------------------------------------------------
extern "C" void kernel_launch(void* const* d_in, const int* in_sizes, int n_in,
                              void* d_out, int out_size) {
    const float* x      = (const float*)d_in[0];
    const float* ln_w   = (const float*)d_in[1];
    const float* ln_b   = (const float*)d_in[2];
    const float* W_in   = (const float*)d_in[3];
    const float* conv_w = (const float*)d_in[4];
    const float* conv_b = (const float*)d_in[5];
    const float* W_xprj = (const float*)d_in[6];
    const float* W_dt   = (const float*)d_in[7];
    const float* b_dt   = (const float*)d_in[8];
    const float* A_log  = (const float*)d_in[9];
    const float* Dw     = (const float*)d_in[10];
    const float* W_out  = (const float*)d_in[11];
    float* out = (float*)d_out;

    float *xn, *xz, *u, *xd, *dl, *y;
    cudaGetSymbolAddress((void**)&xn, g_xn);
    cudaGetSymbolAddress((void**)&xz, g_xz);
    cudaGetSymbolAddress((void**)&u,  g_u);
    cudaGetSymbolAddress((void**)&xd, g_xd);
    cudaGetSymbolAddress((void**)&dl, g_dl);
    cudaGetSymbolAddress((void**)&y,  g_y);

    // 1. layernorm
    ln_kernel<<<BL, 256>>>(x, ln_w, ln_b, xn);

    // 2. xz = xn @ W_in  (silu fused on z half)
    {
        dim3 grid((2 * DI) / 128, BL / 128);
        sgemm_kernel<128,128,16,8,8,1><<<grid, 256>>>(BL, 2*DI, DM, xn, DM,
            W_in, 2*DI, xz, 2*DI, nullptr, nullptr, DI);
    }

    // 3. depthwise conv + bias + silu -> u
    conv_kernel<<<(BL * DI) / 256, 256>>>(conv_w, conv_b);

    // 4. x_dbl = u @ W_xproj  (N=192 -> BN=64 tiles)
    {
        dim3 grid(XPJ / 64, BL / 128);
        sgemm_kernel<128,64,16,8,4,0><<<grid, 256>>>(BL, XPJ, DI, u, DI,
            W_xprj, XPJ, xd, XPJ, nullptr, nullptr, 0);
    }

    // 5. delta = softplus(dt_r @ W_dt + b_dt)
    {
        dim3 grid(DI / 128, BL / 128);
        sgemm_kernel<128,128,16,8,8,2><<<grid, 256>>>(BL, DI, DTR, xd, XPJ,
            W_dt, DI, dl, DI, b_dt, nullptr, 0);
    }

    // 6. selective scan -> y (includes +u*D and *silu(z))
    scan_kernel<<<(Bb * DI) / 8, 256>>>(A_log, Dw);

    // 7. out = y @ W_out + residual
    {
        dim3 grid(DM / 128, BL / 128);
        sgemm_kernel<128,128,16,8,8,3><<<grid, 256>>>(BL, DM, DI, y, DI,
            W_out, DM, out, DM, nullptr, x, 0);
    }
}

// round 2
// speedup vs baseline: 1.8770x; 1.8770x over previous
#include <cuda_runtime.h>
#include <cuda_bf16.h>
#include <cstdint>

// Shapes (fixed by the problem)
#define Bb 4
#define Ll 2048
#define DM 1024
#define DI 2048
#define DS 64
#define DTR 64
#define XPJ 192           // DTR + 2*DS
#define BL  (Bb*Ll)       // 8192

// ---------------- scratch (device globals; no allocation APIs) --------------
__device__ float g_xn[BL * DM];        // layernorm output
__device__ float g_xz[BL * 2 * DI];    // xz = xn @ W_in (cols >= DI hold silu(z))
__device__ float g_u [BL * DI];        // conv+silu output
__device__ float g_xd[BL * XPJ];       // x_dbl
__device__ float g_dl[BL * DI];        // delta (post softplus)
__device__ float g_y [BL * DI];        // scan output * silu(z)

// ---------------- small helpers ---------------------------------------------
__device__ __forceinline__ float siluf(float v) { return v / (1.0f + __expf(-v)); }

__device__ __forceinline__ uint32_t f2tf32(float x) {
    uint32_t u; asm("cvt.rna.tf32.f32 %0, %1;" : "=r"(u) : "f"(x)); return u;
}
__device__ __forceinline__ void cpa16(uint32_t s, const void* g) {
    asm volatile("cp.async.cg.shared.global [%0], [%1], 16;" :: "r"(s), "l"(g));
}
__device__ __forceinline__ void cp_commit() { asm volatile("cp.async.commit_group;"); }
template<int N> __device__ __forceinline__ void cp_wait() {
    asm volatile("cp.async.wait_group %0;" :: "n"(N));
}
__device__ __forceinline__ void mma_tf32(float* c, const uint32_t* a, const uint32_t* b) {
    asm volatile("mma.sync.aligned.m16n8k8.row.col.f32.tf32.tf32.f32 "
        "{%0,%1,%2,%3}, {%4,%5,%6,%7}, {%8,%9}, {%0,%1,%2,%3};"
        : "+f"(c[0]), "+f"(c[1]), "+f"(c[2]), "+f"(c[3])
        : "r"(a[0]), "r"(a[1]), "r"(a[2]), "r"(a[3]), "r"(b[0]), "r"(b[1]));
}

// ---------------- LayerNorm -------------------------------------------------
__global__ void ln_kernel(const float* __restrict__ x,
                          const float* __restrict__ w,
                          const float* __restrict__ b,
                          float* __restrict__ out) {
    int row = blockIdx.x;
    int tid = threadIdx.x;
    const float4* xr = (const float4*)(x + (size_t)row * DM);
    float4 v = xr[tid];

    __shared__ float s1[8], s2[8];
    float sum  = v.x + v.y + v.z + v.w;
    float sumq = v.x*v.x + v.y*v.y + v.z*v.z + v.w*v.w;
    for (int o = 16; o > 0; o >>= 1) {
        sum  += __shfl_xor_sync(0xffffffff, sum,  o);
        sumq += __shfl_xor_sync(0xffffffff, sumq, o);
    }
    if ((tid & 31) == 0) { s1[tid >> 5] = sum; s2[tid >> 5] = sumq; }
    __syncthreads();
    float ts = 0.f, tq = 0.f;
#pragma unroll
    for (int i = 0; i < 8; i++) { ts += s1[i]; tq += s2[i]; }
    float mu  = ts * (1.0f / DM);
    float var = tq * (1.0f / DM) - mu * mu;
    float inv = rsqrtf(var + 1e-5f);

    const float4 wv = ((const float4*)w)[tid];
    const float4 bv = ((const float4*)b)[tid];
    float4 o;
    o.x = (v.x - mu) * inv * wv.x + bv.x;
    o.y = (v.y - mu) * inv * wv.y + bv.y;
    o.z = (v.z - mu) * inv * wv.z + bv.z;
    o.w = (v.w - mu) * inv * wv.w + bv.w;
    ((float4*)(out + (size_t)row * DM))[tid] = o;
}

// ---------------- TF32 tensor-core GEMM -------------------------------------
// C[M,N] = A[M,K] @ B[K,N]   (A,B,C fp32 in memory; tf32 on the tensor pipe)
// MODE 0: plain      MODE 1: silu on cols >= halfN
// MODE 2: softplus(v + bias[col])         MODE 3: v + res[row,col]
template<int BM, int BN, int WARPS_M, int WARPS_N, int WM, int WN, int MODE>
__global__ __launch_bounds__(256) void tf32_gemm(
    int M, int N, int K,
    const float* __restrict__ A, int lda,
    const float* __restrict__ B, int ldb,
    float* __restrict__ C, int ldc,
    const float* __restrict__ bias,
    const float* __restrict__ res,
    int halfN)
{
    constexpr int BK  = 32;
    constexpr int AST = BK + 8;   // 40 floats: conflict-free fragment LDS
    constexpr int BST = BN + 8;
    constexpr int MT  = WM / 16;
    constexpr int NT  = WN / 8;
    static_assert(WARPS_M * WARPS_N == 8, "8 warps");

    extern __shared__ float sm[];
    float* AsBase = sm;                      // [2][BM][AST]
    float* BsBase = sm + 2 * BM * AST;       // [2][BK][BST]

    const int tid  = threadIdx.x;
    const int lane = tid & 31, warp = tid >> 5;
    const int wm = warp / WARPS_N, wn = warp % WARPS_N;
    const int g = lane >> 2, tg = lane & 3;
    const int rowBase = blockIdx.y * BM;
    const int colBase = blockIdx.x * BN;

    constexpr int A_IT = (BM * (BK / 4)) / 256;   // 16B chunks per thread
    constexpr int B_IT = (BK * (BN / 4)) / 256;

    uint32_t sbase;
    asm("{ .reg .u64 t; cvta.to.shared.u64 t, %1; cvt.u32.u64 %0, t; }"
        : "=r"(sbase) : "l"(sm));

    float acc[MT][NT][4];
#pragma unroll
    for (int i = 0; i < MT; i++)
#pragma unroll
        for (int j = 0; j < NT; j++)
#pragma unroll
            for (int q = 0; q < 4; q++) acc[i][j][q] = 0.f;

    const int KT = K / BK;

    // tile loader (issues one cp.async group)
    auto loadTile = [&](int kt, int buf) {
        const float* Ag = A + (size_t)rowBase * lda + kt * BK;
#pragma unroll
        for (int i = 0; i < A_IT; i++) {
            int c = tid + i * 256;
            int r = c >> 3;           // / (BK/4)
            int s = c & 7;
            cpa16(sbase + (uint32_t)((buf * BM * AST + r * AST + s * 4) * 4),
                  Ag + (size_t)r * lda + s * 4);
        }
        const float* Bg = B + (size_t)(kt * BK) * ldb + colBase;
#pragma unroll
        for (int i = 0; i < B_IT; i++) {
            int c = tid + i * 256;
            int r = c / (BN / 4);
            int s = c % (BN / 4);
            cpa16(sbase + (uint32_t)((2 * BM * AST + buf * BK * BST + r * BST + s * 4) * 4),
                  Bg + (size_t)r * ldb + s * 4);
        }
        cp_commit();
    };

    loadTile(0, 0);
    int buf = 0;
    for (int kt = 0; kt < KT; kt++) {
        if (kt + 1 < KT) { loadTile(kt + 1, buf ^ 1); cp_wait<1>(); }
        else             { cp_wait<0>(); }
        __syncthreads();

        const float* Ab = AsBase + buf * BM * AST;
        const float* Bc = BsBase + buf * BK * BST;
#pragma unroll
        for (int ks = 0; ks < 4; ks++) {
            uint32_t af[MT][4], bf[NT][2];
#pragma unroll
            for (int mt = 0; mt < MT; mt++) {
                int m = wm * WM + mt * 16;
                af[mt][0] = f2tf32(Ab[(m + g    ) * AST + ks * 8 + tg    ]);
                af[mt][1] = f2tf32(Ab[(m + g + 8) * AST + ks * 8 + tg    ]);
                af[mt][2] = f2tf32(Ab[(m + g    ) * AST + ks * 8 + tg + 4]);
                af[mt][3] = f2tf32(Ab[(m + g + 8) * AST + ks * 8 + tg + 4]);
            }
#pragma unroll
            for (int nt = 0; nt < NT; nt++) {
                int n = wn * WN + nt * 8;
                bf[nt][0] = f2tf32(Bc[(ks * 8 + tg    ) * BST + n + g]);
                bf[nt][1] = f2tf32(Bc[(ks * 8 + tg + 4) * BST + n + g]);
            }
#pragma unroll
            for (int mt = 0; mt < MT; mt++)
#pragma unroll
                for (int nt = 0; nt < NT; nt++)
                    mma_tf32(acc[mt][nt], af[mt], bf[nt]);
        }
        __syncthreads();
        buf ^= 1;
    }

    // epilogue (float2 stores: c0/c1 are adjacent columns)
#pragma unroll
    for (int mt = 0; mt < MT; mt++) {
#pragma unroll
        for (int half = 0; half < 2; half++) {
            int row = rowBase + wm * WM + mt * 16 + g + half * 8;
#pragma unroll
            for (int nt = 0; nt < NT; nt++) {
                int col = colBase + wn * WN + nt * 8 + 2 * tg;
                float v0 = acc[mt][nt][half * 2 + 0];
                float v1 = acc[mt][nt][half * 2 + 1];
                if (MODE == 1) {
                    if (col >= halfN)     v0 = siluf(v0);
                    if (col + 1 >= halfN) v1 = siluf(v1);
                } else if (MODE == 2) {
                    v0 += bias[col];     v0 = (v0 > 20.0f) ? v0 : log1pf(expf(v0));
                    v1 += bias[col + 1]; v1 = (v1 > 20.0f) ? v1 : log1pf(expf(v1));
                } else if (MODE == 3) {
                    float2 rv = *(const float2*)&res[(size_t)row * ldc + col];
                    v0 += rv.x; v1 += rv.y;
                }
                *(float2*)&C[(size_t)row * ldc + col] = make_float2(v0, v1);
            }
        }
    }
}

// ---------------- depthwise causal conv (k=4) + bias + silu -----------------
__global__ void conv_kernel(const float* __restrict__ cw,
                            const float* __restrict__ cb) {
    int idx = blockIdx.x * blockDim.x + threadIdx.x;
    if (idx >= BL * DI) return;
    int d = idx & (DI - 1);
    int r = idx >> 11;
    int l = r & (Ll - 1);

    float s = cb[d];
    const float* w = cw + d * 4;
#pragma unroll
    for (int k = 0; k < 4; k++) {
        int lt = l - 3 + k;
        if (lt >= 0) s += w[k] * g_xz[(size_t)(r - 3 + k) * (2 * DI) + d];
    }
    g_u[(size_t)r * DI + d] = s / (1.0f + __expf(-s));
}

// ---------------- selective scan: one warp per (b, d) channel ---------------
__global__ __launch_bounds__(256) void scan_kernel(const float* __restrict__ A_log,
                                                   const float* __restrict__ Dw) {
    const int warp = (blockIdx.x * blockDim.x + threadIdx.x) >> 5;
    const int lane = threadIdx.x & 31;
    const int b = warp >> 11;
    const int d = warp & (DI - 1);

    const int n0 = 2 * lane;
    float aa0 = -__expf(A_log[(size_t)d * DS + n0])     * 1.44269504088896f;
    float aa1 = -__expf(A_log[(size_t)d * DS + n0 + 1]) * 1.44269504088896f;
    const float Dd = Dw[d];

    const size_t rowBase = (size_t)b * Ll;
    float h0 = 0.f, h1 = 0.f;

    for (int t = 0; t < Ll; t++) {
        const size_t r = rowBase + t;
        float dt  = g_dl[r * DI + d];
        float ut  = g_u [r * DI + d];
        float zs  = g_xz[r * (2 * DI) + DI + d];
        float2 Bv = *(const float2*)&g_xd[r * XPJ + DTR + n0];
        float2 Cv = *(const float2*)&g_xd[r * XPJ + DTR + DS + n0];

        float e0 = exp2f(dt * aa0);
        float e1 = exp2f(dt * aa1);
        float du = dt * ut;
        h0 = fmaf(h0, e0, du * Bv.x);
        h1 = fmaf(h1, e1, du * Bv.y);
        float p = fmaf(h0, Cv.x, h1 * Cv.y);
#pragma unroll
        for (int o = 16; o > 0; o >>= 1)
            p += __shfl_xor_sync(0xffffffff, p, o);
        if (lane == 0)
            g_y[r * DI + d] = (p + ut * Dd) * zs;
    }
}

// ---------------- launch ----------------------------------------------------
extern "C" void kernel_launch(void* const* d_in, const int* in_sizes, int n_in,
                              void* d_out, int out_size) {
    const float* x      = (const float*)d_in[0];
    const float* ln_w   = (const float*)d_in[1];
    const float* ln_b   = (const float*)d_in[2];
    const float* W_in   = (const float*)d_in[3];
    const float* conv_w = (const float*)d_in[4];
    const float* conv_b = (const float*)d_in[5];
    const float* W_xprj = (const float*)d_in[6];
    const float* W_dt   = (const float*)d_in[7];
    const float* b_dt   = (const float*)d_in[8];
    const float* A_log  = (const float*)d_in[9];
    const float* Dw     = (const float*)d_in[10];
    const float* W_out  = (const float*)d_in[11];
    float* out = (float*)d_out;

    float *xn, *xz, *u, *xd, *dl, *y;
    cudaGetSymbolAddress((void**)&xn, g_xn);
    cudaGetSymbolAddress((void**)&xz, g_xz);
    cudaGetSymbolAddress((void**)&u,  g_u);
    cudaGetSymbolAddress((void**)&xd, g_xd);
    cudaGetSymbolAddress((void**)&dl, g_dl);
    cudaGetSymbolAddress((void**)&y,  g_y);

    // smem sizes (bytes): 2*BM*(BK+8) + 2*BK*(BN+8) floats
    const int SMEM_BIG = (2 * 128 * 40 + 2 * 32 * 136) * 4;  // 75776
    const int SMEM_XPJ = (2 * 128 * 40 + 2 * 32 * 72) * 4;   // 59392

    auto kBig1 = tf32_gemm<128, 128, 2, 4, 64, 32, 1>;
    auto kBig2 = tf32_gemm<128, 128, 2, 4, 64, 32, 2>;
    auto kBig3 = tf32_gemm<128, 128, 2, 4, 64, 32, 3>;
    auto kXpj  = tf32_gemm<128,  64, 4, 2, 32, 32, 0>;
    cudaFuncSetAttribute(kBig1, cudaFuncAttributeMaxDynamicSharedMemorySize, SMEM_BIG);
    cudaFuncSetAttribute(kBig2, cudaFuncAttributeMaxDynamicSharedMemorySize, SMEM_BIG);
    cudaFuncSetAttribute(kBig3, cudaFuncAttributeMaxDynamicSharedMemorySize, SMEM_BIG);
    cudaFuncSetAttribute(kXpj,  cudaFuncAttributeMaxDynamicSharedMemorySize, SMEM_XPJ);

    // 1. layernorm
    ln_kernel<<<BL, 256>>>(x, ln_w, ln_b, xn);

    // 2. xz = xn @ W_in  (silu fused on z half)
    {
        dim3 grid((2 * DI) / 128, BL / 128);
        kBig1<<<grid, 256, SMEM_BIG>>>(BL, 2 * DI, DM, xn, DM,
            W_in, 2 * DI, xz, 2 * DI, nullptr, nullptr, DI);
    }

    // 3. depthwise conv + bias + silu -> u
    conv_kernel<<<(BL * DI) / 256, 256>>>(conv_w, conv_b);

    // 4. x_dbl = u @ W_xproj  (N=192 -> BN=64 tiles)
    {
        dim3 grid(XPJ / 64, BL / 128);
        kXpj<<<grid, 256, SMEM_XPJ>>>(BL, XPJ, DI, u, DI,
            W_xprj, XPJ, xd, XPJ, nullptr, nullptr, 0);
    }

    // 5. delta = softplus(dt_r @ W_dt + b_dt)
    {
        dim3 grid(DI / 128, BL / 128);
        kBig2<<<grid, 256, SMEM_BIG>>>(BL, DI, DTR, xd, XPJ,
            W_dt, DI, dl, DI, b_dt, nullptr, 0);
    }

    // 6. selective scan -> y (includes +u*D and *silu(z))
    scan_kernel<<<(Bb * DI) / 8, 256>>>(A_log, Dw);

    // 7. out = y @ W_out + residual
    {
        dim3 grid(DM / 128, BL / 128);
        kBig3<<<grid, 256, SMEM_BIG>>>(BL, DM, DI, y, DI,
            W_out, DM, out, DM, nullptr, x, 0);
    }
}